// round 5
// baseline (speedup 1.0000x reference)
#include <cuda_runtime.h>
#include <cstdint>

#define HID 128
#define NJOB 100000
#define MAXSRC 20000
#define MAXY   90000          // 20k+20k+20k+20k+10k source rows
#define EMAX   800000
#define TOTE   (5 * EMAX)
#define NCNT   (5 * NJOB)

// ---------------- scratch (static device globals; no allocation) ----------------
__device__ float g_y[MAXY * HID];       // transformed source feats, all 5 relations
__device__ int   g_icnt[NCNT];          // per (rel, job) edge counts
__device__ int   g_off[NCNT];           // exclusive-scan offsets into g_eidx
__device__ int   g_cur[NCNT];           // fill cursors (copy of g_off)
__device__ int   g_eidx[TOTE];          // CSR payload: row index into g_y
__device__ int   g_bsum[256];           // scan block sums
__device__ float g_WrS[HID * HID];      // sum of the 5 Wr matrices
__device__ float g_blS[HID];            // sum of the 5 biases

// ---------------- tiny: WrS = sum Wr_r, blS = sum bl_r ----------------
__global__ void sum_wr_kernel(const float* __restrict__ w0, const float* __restrict__ w1,
                              const float* __restrict__ w2, const float* __restrict__ w3,
                              const float* __restrict__ w4,
                              const float* __restrict__ b0, const float* __restrict__ b1,
                              const float* __restrict__ b2, const float* __restrict__ b3,
                              const float* __restrict__ b4)
{
    int i = blockIdx.x * blockDim.x + threadIdx.x;
    if (i < HID * HID) g_WrS[i] = w0[i] + w1[i] + w2[i] + w3[i] + w4[i];
    if (i < HID)       g_blS[i] = b0[i] + b1[i] + b2[i] + b3[i] + b4[i];
}

__global__ void zero4_kernel(int4* __restrict__ p, int n4)
{
    int i = blockIdx.x * blockDim.x + threadIdx.x;
    if (i < n4) p[i] = make_int4(0, 0, 0, 0);
}

// ---------------- GEMM: Y[r,c] = sum_k X[r,k] * W[c,k] (+ bias[c]) ----------------
// 256 threads: col = tid&127, row-half = tid>>7; 64 rows per block (32 per half).
// W staged in shared with 130-float pitch; X tile in shared (broadcast reads).
// Inner product uses packed fma.rn.f32x2 over even/odd k lanes.
__global__ void __launch_bounds__(256) gemm128_kernel(
    const float* __restrict__ X, const float* __restrict__ W,
    const float* __restrict__ bias, float* __restrict__ Y, int nrows)
{
    constexpr int TM = 64;          // rows per block
    constexpr int TT = 32;          // rows per thread (TM/2)
    extern __shared__ float smem[];
    float* Wsh = smem;              // [128][130]
    float* Xs  = smem + 128 * 130;  // [TM][128]
    const int tid  = threadIdx.x;
    const int col  = tid & 127;
    const int half = tid >> 7;

    #pragma unroll 4
    for (int i = tid; i < HID * HID; i += 256)
        Wsh[(i >> 7) * 130 + (i & 127)] = W[i];

    const int row0 = blockIdx.x * TM;
    #pragma unroll 4
    for (int i = tid; i < TM * HID; i += 256) {
        int r = row0 + (i >> 7);
        Xs[i] = (r < nrows) ? X[r * HID + (i & 127)] : 0.f;
    }
    __syncthreads();

    unsigned long long acc2[TT];
    #pragma unroll
    for (int m = 0; m < TT; m++) acc2[m] = 0ull;

    const unsigned long long* wrow =
        reinterpret_cast<const unsigned long long*>(Wsh + col * 130);
    const float* xbase = Xs + (half * TT) * HID;

    for (int k2 = 0; k2 < HID / 2; k2++) {
        unsigned long long w2 = wrow[k2];
        #pragma unroll
        for (int m = 0; m < TT; m++) {
            unsigned long long x2 =
                *reinterpret_cast<const unsigned long long*>(xbase + m * HID + 2 * k2);
            asm("fma.rn.f32x2 %0, %1, %2, %0;" : "+l"(acc2[m]) : "l"(x2), "l"(w2));
        }
    }

    float bv = bias ? bias[col] : 0.f;
    #pragma unroll
    for (int m = 0; m < TT; m++) {
        int r = row0 + half * TT + m;
        if (r < nrows) {
            float lo = __uint_as_float((unsigned)(acc2[m] & 0xffffffffull));
            float hi = __uint_as_float((unsigned)(acc2[m] >> 32));
            Y[r * HID + col] = lo + hi + bv;
        }
    }
}

// ---------------- CSR build ----------------
__global__ void hist_kernel(const int* __restrict__ dst, int n, int* __restrict__ cnt)
{
    int i = blockIdx.x * blockDim.x + threadIdx.x;
    if (i < n) atomicAdd(cnt + __ldg(dst + i), 1);
}

// exclusive scan, 3 kernels. scan1: per-block (1024 thr x 4 items) local scan + block sum
__global__ void __launch_bounds__(1024) scan1_kernel(const int* __restrict__ in,
                                                     int* __restrict__ out,
                                                     int* __restrict__ bsum, int n)
{
    __shared__ int sh[1024];
    int base = blockIdx.x * 4096 + threadIdx.x * 4;
    int4 v = make_int4(0, 0, 0, 0);
    if (base < n) v = *reinterpret_cast<const int4*>(in + base);   // n divisible by 4
    int s = v.x + v.y + v.z + v.w;
    sh[threadIdx.x] = s;
    __syncthreads();
    for (int d = 1; d < 1024; d <<= 1) {
        int t = (threadIdx.x >= d) ? sh[threadIdx.x - d] : 0;
        __syncthreads();
        sh[threadIdx.x] += t;
        __syncthreads();
    }
    if (threadIdx.x == 1023) bsum[blockIdx.x] = sh[1023];
    int e = sh[threadIdx.x] - s;                                   // exclusive
    if (base < n) {
        int4 o;
        o.x = e; o.y = e + v.x; o.z = o.y + v.y; o.w = o.z + v.z;
        *reinterpret_cast<int4*>(out + base) = o;
    }
}

__global__ void __launch_bounds__(1024) scan2_kernel(int* __restrict__ bsum, int nb)
{
    __shared__ int sh[1024];
    int v = (threadIdx.x < nb) ? bsum[threadIdx.x] : 0;
    sh[threadIdx.x] = v;
    __syncthreads();
    for (int d = 1; d < 1024; d <<= 1) {
        int t = (threadIdx.x >= d) ? sh[threadIdx.x - d] : 0;
        __syncthreads();
        sh[threadIdx.x] += t;
        __syncthreads();
    }
    if (threadIdx.x < nb) bsum[threadIdx.x] = sh[threadIdx.x] - v; // exclusive
}

// add block bases; also produce cursor copy for the fill pass
__global__ void __launch_bounds__(1024) scan3_kernel(int* __restrict__ out,
                                                     int* __restrict__ cur,
                                                     const int* __restrict__ bsum, int n)
{
    int base = blockIdx.x * 4096 + threadIdx.x * 4;
    if (base < n) {
        int a = bsum[blockIdx.x];
        int4 v = *reinterpret_cast<int4*>(out + base);
        v.x += a; v.y += a; v.z += a; v.w += a;
        *reinterpret_cast<int4*>(out + base) = v;
        *reinterpret_cast<int4*>(cur + base) = v;
    }
}

__global__ void fill_kernel(const int* __restrict__ src, const int* __restrict__ dst,
                            int n, int* __restrict__ cur, int yofs)
{
    int i = blockIdx.x * blockDim.x + threadIdx.x;
    if (i < n) {
        int d = __ldg(dst + i);
        int p = atomicAdd(cur + d, 1);
        g_eidx[p] = yofs + __ldg(src + i);
    }
}

// ---------------- gather: warp per job; 5 relations; mean; +base; relu ----------------
__global__ void __launch_bounds__(256) gather_kernel(const float* __restrict__ y,
                                                     float* __restrict__ out, int njob)
{
    int g = blockIdx.x * blockDim.x + threadIdx.x;
    int j = g >> 5;
    if (j >= njob) return;
    int lane = g & 31;

    float4 tot = reinterpret_cast<const float4*>(out + (size_t)j * HID)[lane]; // base term

    #pragma unroll
    for (int r = 0; r < 5; r++) {
        int idx = r * NJOB + j;
        int c     = __ldg(g_icnt + idx);
        int start = __ldg(g_off  + idx);
        float4 s = make_float4(0.f, 0.f, 0.f, 0.f);
        for (int b = 0; b < c; b += 32) {
            int nn = c - b; if (nn > 32) nn = 32;
            int ei = 0;
            if (lane < nn) ei = __ldg(g_eidx + start + b + lane);
            for (int k = 0; k < nn; k++) {
                int row = __shfl_sync(0xffffffffu, ei, k);
                float4 v = __ldg(reinterpret_cast<const float4*>(y + (size_t)row * HID) + lane);
                s.x += v.x; s.y += v.y; s.z += v.z; s.w += v.w;
            }
        }
        float inv = 1.0f / fmaxf((float)c, 1.0f);
        tot.x = fmaf(s.x, inv, tot.x);
        tot.y = fmaf(s.y, inv, tot.y);
        tot.z = fmaf(s.z, inv, tot.z);
        tot.w = fmaf(s.w, inv, tot.w);
    }
    tot.x = fmaxf(tot.x, 0.f); tot.y = fmaxf(tot.y, 0.f);
    tot.z = fmaxf(tot.z, 0.f); tot.w = fmaxf(tot.w, 0.f);
    reinterpret_cast<float4*>(out + (size_t)j * HID)[lane] = tot;
}

// ---------------- host ----------------
extern "C" void kernel_launch(void* const* d_in, const int* in_sizes, int n_in,
                              void* d_out, int out_size)
{
    const float* x_job = (const float*)d_in[0];
    const float* xtab[5];
    xtab[0] = (const float*)d_in[1];  // station
    xtab[1] = (const float*)d_in[1];  // station
    xtab[2] = (const float*)d_in[2];  // machine
    xtab[3] = (const float*)d_in[2];  // machine
    xtab[4] = (const float*)d_in[3];  // robot
    int nsrc[5];
    nsrc[0] = in_sizes[1] / HID; nsrc[1] = nsrc[0];
    nsrc[2] = in_sizes[2] / HID; nsrc[3] = nsrc[2];
    nsrc[4] = in_sizes[3] / HID;
    int yofs[5];
    yofs[0] = 0;
    for (int r = 1; r < 5; r++) yofs[r] = yofs[r - 1] + nsrc[r - 1];

    const int *src[5], *dst[5];
    const float *Wl[5], *bl[5], *Wr[5];
    int nedge[5];
    // Detect input ordering: dict order (src,dst,Wl,bl,Wr per relation) has a
    // 16384-element tensor at index 6; signature order has 800000 there.
    bool dict = (in_sizes[6] == HID * HID);
    for (int r = 0; r < 5; r++) {
        if (dict) {
            src[r] = (const int*)d_in[4 + 5 * r];
            dst[r] = (const int*)d_in[5 + 5 * r];
            Wl[r]  = (const float*)d_in[6 + 5 * r];
            bl[r]  = (const float*)d_in[7 + 5 * r];
            Wr[r]  = (const float*)d_in[8 + 5 * r];
            nedge[r] = in_sizes[4 + 5 * r];
        } else {
            src[r] = (const int*)d_in[4 + 2 * r];
            dst[r] = (const int*)d_in[5 + 2 * r];
            Wl[r]  = (const float*)d_in[14 + 3 * r];
            bl[r]  = (const float*)d_in[15 + 3 * r];
            Wr[r]  = (const float*)d_in[16 + 3 * r];
            nedge[r] = in_sizes[4 + 2 * r];
        }
    }

    float *yp, *WrSp, *blSp;
    int *icntp, *offp, *curp, *bsump;
    cudaGetSymbolAddress((void**)&yp,    g_y);
    cudaGetSymbolAddress((void**)&WrSp,  g_WrS);
    cudaGetSymbolAddress((void**)&blSp,  g_blS);
    cudaGetSymbolAddress((void**)&icntp, g_icnt);
    cudaGetSymbolAddress((void**)&offp,  g_off);
    cudaGetSymbolAddress((void**)&curp,  g_cur);
    cudaGetSymbolAddress((void**)&bsump, g_bsum);

    const int SMEM = (128 * 130 + 64 * 128) * (int)sizeof(float);
    cudaFuncSetAttribute(gemm128_kernel, cudaFuncAttributeMaxDynamicSharedMemorySize, SMEM);

    int njob = out_size / HID;
    int n5 = 5 * njob;                      // count-array length (divisible by 4)
    int nb = (n5 + 4095) / 4096;            // scan blocks (<= 1024)

    // Fold all 5 Wr + biases into one matrix/vector.
    sum_wr_kernel<<<64, 256>>>(Wr[0], Wr[1], Wr[2], Wr[3], Wr[4],
                               bl[0], bl[1], bl[2], bl[3], bl[4]);

    // Zero per-(rel,job) counters.
    zero4_kernel<<<(n5 / 4 + 255) / 256, 256>>>(reinterpret_cast<int4*>(icntp), n5 / 4);

    // Base term: out = x_job @ WrS^T + blS (also initializes poisoned d_out).
    gemm128_kernel<<<(njob + 63) / 64, 256, SMEM>>>(x_job, WrSp, blSp, (float*)d_out, njob);

    // Transform all source tables: y_r = x_src_r @ Wl_r^T (10-20k rows each).
    for (int r = 0; r < 5; r++)
        gemm128_kernel<<<(nsrc[r] + 63) / 64, 256, SMEM>>>(
            xtab[r], Wl[r], nullptr, yp + (size_t)yofs[r] * HID, nsrc[r]);

    // Histogram destinations per relation.
    for (int r = 0; r < 5; r++)
        hist_kernel<<<(nedge[r] + 255) / 256, 256>>>(dst[r], nedge[r], icntp + r * NJOB);

    // Global exclusive scan over all 5*njob counts (region bases fall out).
    scan1_kernel<<<nb, 1024>>>(icntp, offp, bsump, n5);
    scan2_kernel<<<1, 1024>>>(bsump, nb);
    scan3_kernel<<<nb, 1024>>>(offp, curp, bsump, n5);

    // Fill CSR payload (y-row index, relation offset folded in).
    for (int r = 0; r < 5; r++)
        fill_kernel<<<(nedge[r] + 255) / 256, 256>>>(src[r], dst[r], nedge[r],
                                                     curp + r * NJOB, yofs[r]);

    // Gather + mean + base + relu, one pass.
    gather_kernel<<<(njob * 32 + 255) / 256, 256>>>(yp, (float*)d_out, njob);
}

// round 7
// speedup vs baseline: 1.4294x; 1.4294x over previous
#include <cuda_runtime.h>
#include <cuda_fp16.h>
#include <cstdint>

#define HID 128
#define NJOB 100000
#define MAXY   90000          // 20k+20k+20k+20k+10k source rows
#define EMAX   800000
#define TOTE   (5 * EMAX)
#define NCNT   (5 * NJOB)

// ---------------- scratch (static device globals; no allocation) ----------------
__device__ __half g_y[MAXY * HID];      // transformed source feats (fp16), all 5 relations
__device__ int   g_icnt[NCNT];          // per (rel, job) edge counts
__device__ int   g_off[NCNT];           // exclusive-scan offsets into g_eidx
__device__ int   g_cur[NCNT];           // fill cursors (copy of g_off)
__device__ int   g_eidx[TOTE];          // CSR payload: row index into g_y
__device__ int   g_bsum[256];           // scan block sums
__device__ float g_WrS[HID * HID];      // sum of the 5 Wr matrices
__device__ float g_blS[HID];            // sum of the 5 biases

__device__ __forceinline__ unsigned long long pk2(float a, float b)
{
    return (unsigned long long)__float_as_uint(a) |
           ((unsigned long long)__float_as_uint(b) << 32);
}

// ---------------- tiny: WrS = sum Wr_r, blS = sum bl_r ----------------
__global__ void sum_wr_kernel(const float* __restrict__ w0, const float* __restrict__ w1,
                              const float* __restrict__ w2, const float* __restrict__ w3,
                              const float* __restrict__ w4,
                              const float* __restrict__ b0, const float* __restrict__ b1,
                              const float* __restrict__ b2, const float* __restrict__ b3,
                              const float* __restrict__ b4)
{
    int i = blockIdx.x * blockDim.x + threadIdx.x;
    if (i < HID * HID) g_WrS[i] = w0[i] + w1[i] + w2[i] + w3[i] + w4[i];
    if (i < HID)       g_blS[i] = b0[i] + b1[i] + b2[i] + b3[i] + b4[i];
}

__global__ void zero4_kernel(int4* __restrict__ p, int n4)
{
    int i = blockIdx.x * blockDim.x + threadIdx.x;
    if (i < n4) p[i] = make_int4(0, 0, 0, 0);
}

// ---------------- GEMM: C[r][c] = sum_k X[r][k] * W[c][k] (+ bias[c]) ----------------
// Outer-product register tiling: 256 threads, 64 rows x 128 cols per block,
// per-thread 8 rows (broadcast A) x 4 cols (strided W). K chunked by 32 through
// shared memory, values stored as (k even, k odd) f32 pairs for fma.rn.f32x2.
// 12 shared loads per 32 FFMA2 -> load pipelining instead of per-FMA LDS stalls.
template <bool HALF_OUT>
__global__ void __launch_bounds__(256, 2) gemm_op_kernel(
    const float* __restrict__ X, const float* __restrict__ W,
    const float* __restrict__ bias, void* __restrict__ Yv, int nrows)
{
    constexpr int KC2 = 16;                         // k-pairs per chunk (32 k)
    __shared__ unsigned long long As2[KC2][66];     // [k2][row]  (pitch 66: 16B-aligned rows)
    __shared__ unsigned long long Ws2[KC2][130];    // [k2][col]

    const int tid = threadIdx.x;
    const int tx  = tid & 31;     // col lane: cols tx + 32*i
    const int ty  = tid >> 5;     // row group: rows ty*8 .. +7
    const int row0 = blockIdx.x * 64;

    unsigned long long acc[8][4];
    #pragma unroll
    for (int j = 0; j < 8; j++)
        #pragma unroll
        for (int i = 0; i < 4; i++) acc[j][i] = 0ull;

    for (int kc = 0; kc < HID; kc += 32) {
        __syncthreads();
        // A chunk: 64 rows x 32 k = 512 float4; coalesced (8 lanes per row).
        #pragma unroll
        for (int b = 0; b < 2; b++) {
            int f = tid + b * 256;
            int q = f & 7;            // which float4 in the 32-k chunk
            int r = f >> 3;           // row 0..63
            int gr = row0 + r;
            float4 v = make_float4(0.f, 0.f, 0.f, 0.f);
            if (gr < nrows)
                v = *reinterpret_cast<const float4*>(X + (size_t)gr * HID + kc + q * 4);
            As2[2 * q][r]     = pk2(v.x, v.y);
            As2[2 * q + 1][r] = pk2(v.z, v.w);
        }
        // W chunk: 128 cols x 32 k = 1024 float4; coalesced.
        #pragma unroll
        for (int b = 0; b < 4; b++) {
            int f = tid + b * 256;
            int q = f & 7;
            int c = f >> 3;           // col 0..127
            float4 v = *reinterpret_cast<const float4*>(W + c * HID + kc + q * 4);
            Ws2[2 * q][c]     = pk2(v.x, v.y);
            Ws2[2 * q + 1][c] = pk2(v.z, v.w);
        }
        __syncthreads();

        #pragma unroll
        for (int k2 = 0; k2 < KC2; k2++) {
            unsigned long long a2[8], w2[4];
            #pragma unroll
            for (int j = 0; j < 8; j++) a2[j] = As2[k2][ty * 8 + j];   // broadcast
            #pragma unroll
            for (int i = 0; i < 4; i++) w2[i] = Ws2[k2][tx + 32 * i];  // dense LDS.64
            #pragma unroll
            for (int j = 0; j < 8; j++)
                #pragma unroll
                for (int i = 0; i < 4; i++)
                    asm("fma.rn.f32x2 %0, %1, %2, %0;"
                        : "+l"(acc[j][i]) : "l"(a2[j]), "l"(w2[i]));
        }
    }

    #pragma unroll
    for (int j = 0; j < 8; j++) {
        int r = row0 + ty * 8 + j;
        if (r < nrows) {
            #pragma unroll
            for (int i = 0; i < 4; i++) {
                int c = tx + 32 * i;
                float lo = __uint_as_float((unsigned)(acc[j][i] & 0xffffffffull));
                float hi = __uint_as_float((unsigned)(acc[j][i] >> 32));
                float v = lo + hi + (bias ? bias[c] : 0.f);
                if (HALF_OUT)
                    reinterpret_cast<__half*>(Yv)[(size_t)r * HID + c] = __float2half_rn(v);
                else
                    reinterpret_cast<float*>(Yv)[(size_t)r * HID + c] = v;
            }
        }
    }
}

// ---------------- CSR build ----------------
__global__ void hist_kernel(const int* __restrict__ dst, int n, int* __restrict__ cnt)
{
    int i = blockIdx.x * blockDim.x + threadIdx.x;
    if (i < n) atomicAdd(cnt + __ldg(dst + i), 1);
}

__global__ void __launch_bounds__(1024) scan1_kernel(const int* __restrict__ in,
                                                     int* __restrict__ out,
                                                     int* __restrict__ bsum, int n)
{
    __shared__ int sh[1024];
    int base = blockIdx.x * 4096 + threadIdx.x * 4;
    int4 v = make_int4(0, 0, 0, 0);
    if (base < n) v = *reinterpret_cast<const int4*>(in + base);   // n divisible by 4
    int s = v.x + v.y + v.z + v.w;
    sh[threadIdx.x] = s;
    __syncthreads();
    for (int d = 1; d < 1024; d <<= 1) {
        int t = (threadIdx.x >= d) ? sh[threadIdx.x - d] : 0;
        __syncthreads();
        sh[threadIdx.x] += t;
        __syncthreads();
    }
    if (threadIdx.x == 1023) bsum[blockIdx.x] = sh[1023];
    int e = sh[threadIdx.x] - s;                                   // exclusive
    if (base < n) {
        int4 o;
        o.x = e; o.y = e + v.x; o.z = o.y + v.y; o.w = o.z + v.z;
        *reinterpret_cast<int4*>(out + base) = o;
    }
}

__global__ void __launch_bounds__(1024) scan2_kernel(int* __restrict__ bsum, int nb)
{
    __shared__ int sh[1024];
    int v = (threadIdx.x < nb) ? bsum[threadIdx.x] : 0;
    sh[threadIdx.x] = v;
    __syncthreads();
    for (int d = 1; d < 1024; d <<= 1) {
        int t = (threadIdx.x >= d) ? sh[threadIdx.x - d] : 0;
        __syncthreads();
        sh[threadIdx.x] += t;
        __syncthreads();
    }
    if (threadIdx.x < nb) bsum[threadIdx.x] = sh[threadIdx.x] - v; // exclusive
}

__global__ void __launch_bounds__(1024) scan3_kernel(int* __restrict__ out,
                                                     int* __restrict__ cur,
                                                     const int* __restrict__ bsum, int n)
{
    int base = blockIdx.x * 4096 + threadIdx.x * 4;
    if (base < n) {
        int a = bsum[blockIdx.x];
        int4 v = *reinterpret_cast<int4*>(out + base);
        v.x += a; v.y += a; v.z += a; v.w += a;
        *reinterpret_cast<int4*>(out + base) = v;
        *reinterpret_cast<int4*>(cur + base) = v;
    }
}

__global__ void fill_kernel(const int* __restrict__ src, const int* __restrict__ dst,
                            int n, int* __restrict__ cur, int yofs)
{
    int i = blockIdx.x * blockDim.x + threadIdx.x;
    if (i < n) {
        int d = __ldg(dst + i);
        int p = atomicAdd(cur + d, 1);
        g_eidx[p] = yofs + __ldg(src + i);
    }
}

// ---------------- gather: warp per job; fp16 rows; 2 edges per iteration ----------------
// lanes 0-15 handle edge k, lanes 16-31 edge k+1; each lane loads 16B (8 halves)
// of its edge's y row; shfl_xor(16) merges the two edge-subsets at the end.
__global__ void __launch_bounds__(256) gather_kernel(const __half* __restrict__ y,
                                                     float* __restrict__ out, int njob)
{
    int g = blockIdx.x * blockDim.x + threadIdx.x;
    int j = g >> 5;
    if (j >= njob) return;
    int lane = g & 31;
    int sub  = lane >> 4;       // which edge of the pair
    int hl   = lane & 15;       // column block: cols hl*8 .. +7

    float acc[8];
    #pragma unroll
    for (int i = 0; i < 8; i++) acc[i] = 0.f;

    #pragma unroll
    for (int r = 0; r < 5; r++) {
        int idx   = r * NJOB + j;
        int c     = __ldg(g_icnt + idx);
        int start = __ldg(g_off  + idx);
        float s8[8];
        #pragma unroll
        for (int i = 0; i < 8; i++) s8[i] = 0.f;

        for (int b = 0; b < c; b += 32) {
            int nn = c - b; if (nn > 32) nn = 32;
            int ei = 0;
            if (lane < nn) ei = __ldg(g_eidx + start + b + lane);
            for (int k = 0; k < nn; k += 2) {
                int kk = k + sub;
                int row = __shfl_sync(0xffffffffu, ei, kk);
                if (kk < nn) {
                    uint4 v = __ldg(reinterpret_cast<const uint4*>(
                        y + (size_t)row * HID + hl * 8));
                    const __half2* h2 = reinterpret_cast<const __half2*>(&v);
                    #pragma unroll
                    for (int t = 0; t < 4; t++) {
                        float2 f = __half22float2(h2[t]);
                        s8[2 * t]     += f.x;
                        s8[2 * t + 1] += f.y;
                    }
                }
            }
        }
        float inv = 1.0f / fmaxf((float)c, 1.0f);
        #pragma unroll
        for (int i = 0; i < 8; i++) acc[i] = fmaf(s8[i], inv, acc[i]);
    }

    // merge the two edge-subsets (lanes L and L+16 hold the same columns)
    #pragma unroll
    for (int i = 0; i < 8; i++) acc[i] += __shfl_xor_sync(0xffffffffu, acc[i], 16);

    if (lane < 16) {
        float4* op = reinterpret_cast<float4*>(out + (size_t)j * HID + hl * 8);
        float4 o0 = op[0];
        float4 o1 = op[1];
        o0.x = fmaxf(o0.x + acc[0], 0.f); o0.y = fmaxf(o0.y + acc[1], 0.f);
        o0.z = fmaxf(o0.z + acc[2], 0.f); o0.w = fmaxf(o0.w + acc[3], 0.f);
        o1.x = fmaxf(o1.x + acc[4], 0.f); o1.y = fmaxf(o1.y + acc[5], 0.f);
        o1.z = fmaxf(o1.z + acc[6], 0.f); o1.w = fmaxf(o1.w + acc[7], 0.f);
        op[0] = o0;
        op[1] = o1;
    }
}

// ---------------- host ----------------
extern "C" void kernel_launch(void* const* d_in, const int* in_sizes, int n_in,
                              void* d_out, int out_size)
{
    const float* x_job = (const float*)d_in[0];
    const float* xtab[5];
    xtab[0] = (const float*)d_in[1];  // station
    xtab[1] = (const float*)d_in[1];  // station
    xtab[2] = (const float*)d_in[2];  // machine
    xtab[3] = (const float*)d_in[2];  // machine
    xtab[4] = (const float*)d_in[3];  // robot
    int nsrc[5];
    nsrc[0] = in_sizes[1] / HID; nsrc[1] = nsrc[0];
    nsrc[2] = in_sizes[2] / HID; nsrc[3] = nsrc[2];
    nsrc[4] = in_sizes[3] / HID;
    int yofs[5];
    yofs[0] = 0;
    for (int r = 1; r < 5; r++) yofs[r] = yofs[r - 1] + nsrc[r - 1];

    const int *src[5], *dst[5];
    const float *Wl[5], *bl[5], *Wr[5];
    int nedge[5];
    // Detect input ordering: dict order (src,dst,Wl,bl,Wr per relation) has a
    // 16384-element tensor at index 6; signature order has 800000 there.
    bool dict = (in_sizes[6] == HID * HID);
    for (int r = 0; r < 5; r++) {
        if (dict) {
            src[r] = (const int*)d_in[4 + 5 * r];
            dst[r] = (const int*)d_in[5 + 5 * r];
            Wl[r]  = (const float*)d_in[6 + 5 * r];
            bl[r]  = (const float*)d_in[7 + 5 * r];
            Wr[r]  = (const float*)d_in[8 + 5 * r];
            nedge[r] = in_sizes[4 + 5 * r];
        } else {
            src[r] = (const int*)d_in[4 + 2 * r];
            dst[r] = (const int*)d_in[5 + 2 * r];
            Wl[r]  = (const float*)d_in[14 + 3 * r];
            bl[r]  = (const float*)d_in[15 + 3 * r];
            Wr[r]  = (const float*)d_in[16 + 3 * r];
            nedge[r] = in_sizes[4 + 2 * r];
        }
    }

    __half* yp;
    float *WrSp, *blSp;
    int *icntp, *offp, *curp, *bsump;
    cudaGetSymbolAddress((void**)&yp,    g_y);
    cudaGetSymbolAddress((void**)&WrSp,  g_WrS);
    cudaGetSymbolAddress((void**)&blSp,  g_blS);
    cudaGetSymbolAddress((void**)&icntp, g_icnt);
    cudaGetSymbolAddress((void**)&offp,  g_off);
    cudaGetSymbolAddress((void**)&curp,  g_cur);
    cudaGetSymbolAddress((void**)&bsump, g_bsum);

    int njob = out_size / HID;
    int n5 = 5 * njob;                      // count-array length (divisible by 4)
    int nb = (n5 + 4095) / 4096;            // scan blocks (<= 256)

    // Fold all 5 Wr + biases into one matrix/vector.
    sum_wr_kernel<<<64, 256>>>(Wr[0], Wr[1], Wr[2], Wr[3], Wr[4],
                               bl[0], bl[1], bl[2], bl[3], bl[4]);

    // Zero per-(rel,job) counters.
    zero4_kernel<<<(n5 / 4 + 255) / 256, 256>>>(reinterpret_cast<int4*>(icntp), n5 / 4);

    // Base term: out = x_job @ WrS^T + blS (also initializes poisoned d_out).
    gemm_op_kernel<false><<<(njob + 63) / 64, 256>>>(x_job, WrSp, blSp, d_out, njob);

    // Transform all source tables: y_r = x_src_r @ Wl_r^T (fp16 output).
    for (int r = 0; r < 5; r++)
        gemm_op_kernel<true><<<(nsrc[r] + 63) / 64, 256>>>(
            xtab[r], Wl[r], nullptr, yp + (size_t)yofs[r] * HID, nsrc[r]);

    // Histogram destinations per relation.
    for (int r = 0; r < 5; r++)
        hist_kernel<<<(nedge[r] + 255) / 256, 256>>>(dst[r], nedge[r], icntp + r * NJOB);

    // Global exclusive scan over all 5*njob counts (region bases fall out).
    scan1_kernel<<<nb, 1024>>>(icntp, offp, bsump, n5);
    scan2_kernel<<<1, 1024>>>(bsump, nb);
    scan3_kernel<<<nb, 1024>>>(offp, curp, bsump, n5);

    // Fill CSR payload (y-row index, relation offset folded in).
    for (int r = 0; r < 5; r++)
        fill_kernel<<<(nedge[r] + 255) / 256, 256>>>(src[r], dst[r], nedge[r],
                                                     curp + r * NJOB, yofs[r]);

    // Gather + mean + base + relu, one pass.
    gather_kernel<<<(njob * 32 + 255) / 256, 256>>>(yp, (float*)d_out, njob);
}

// round 9
// speedup vs baseline: 2.0082x; 1.4049x over previous
#include <cuda_runtime.h>
#include <cuda_fp16.h>
#include <cstdint>

#define HID 128
#define NJOB 100000
#define MAXY   90000          // 20k+20k+20k+20k+10k source rows
#define EMAX   800000
#define TOTE   (5 * EMAX)
#define NCNT   (5 * NJOB)

// ---------------- scratch (static device globals; no allocation) ----------------
__device__ __half g_y[MAXY * HID];      // transformed source feats (fp16), all 5 relations
__device__ int   g_icnt[NCNT];          // per (rel, job) edge counts
__device__ int   g_off[NCNT];           // exclusive-scan offsets into g_eidx
__device__ int   g_cur[NCNT];           // fill cursors (copy of g_off)
__device__ int   g_eidx[TOTE];          // CSR payload: row index into g_y
__device__ int   g_bsum[256];           // scan block sums
__device__ float g_WrS[HID * HID];      // sum of the 5 Wr matrices
__device__ float g_blS[HID];            // sum of the 5 biases

// ---------------- tiny: WrS = sum Wr_r, blS = sum bl_r ----------------
__global__ void sum_wr_kernel(const float* __restrict__ w0, const float* __restrict__ w1,
                              const float* __restrict__ w2, const float* __restrict__ w3,
                              const float* __restrict__ w4,
                              const float* __restrict__ b0, const float* __restrict__ b1,
                              const float* __restrict__ b2, const float* __restrict__ b3,
                              const float* __restrict__ b4)
{
    int i = blockIdx.x * blockDim.x + threadIdx.x;
    if (i < HID * HID) g_WrS[i] = w0[i] + w1[i] + w2[i] + w3[i] + w4[i];
    if (i < HID)       g_blS[i] = b0[i] + b1[i] + b2[i] + b3[i] + b4[i];
}

__global__ void zero4_kernel(int4* __restrict__ p, int n4)
{
    int i = blockIdx.x * blockDim.x + threadIdx.x;
    if (i < n4) p[i] = make_int4(0, 0, 0, 0);
}

// ---------------- tensor-core GEMM: C[r][c] = sum_k X[r][k] * W[c][k] (+bias) ----------
// mma.sync m16n8k16 f16->f32. Block: 256 thr = 8 warps, 128 rows x 128 cols.
// Warp tile 32x64 (2 m16 x 8 n8). X,W converted fp32->fp16 into smem
// (pitch 136 halves = 272 B: 16B-aligned rows, conflict-free ldmatrix).
// W is K-major = col-major B, matching mma's row.col directly.

__device__ __forceinline__ uint32_t smem_u32(const void* p)
{
    return (uint32_t)__cvta_generic_to_shared(p);
}

__device__ __forceinline__ void ldsm4(uint32_t& r0, uint32_t& r1, uint32_t& r2,
                                      uint32_t& r3, uint32_t addr)
{
    asm volatile("ldmatrix.sync.aligned.m8n8.x4.shared.b16 {%0,%1,%2,%3}, [%4];"
                 : "=r"(r0), "=r"(r1), "=r"(r2), "=r"(r3) : "r"(addr));
}

__device__ __forceinline__ void mma16816(float* c, uint32_t a0, uint32_t a1,
                                         uint32_t a2, uint32_t a3,
                                         uint32_t b0, uint32_t b1)
{
    asm volatile(
        "mma.sync.aligned.m16n8k16.row.col.f32.f16.f16.f32 "
        "{%0,%1,%2,%3}, {%4,%5,%6,%7}, {%8,%9}, {%0,%1,%2,%3};"
        : "+f"(c[0]), "+f"(c[1]), "+f"(c[2]), "+f"(c[3])
        : "r"(a0), "r"(a1), "r"(a2), "r"(a3), "r"(b0), "r"(b1));
}

#define SPITCH 136   // halves per smem row (128 + 8 pad)

template <bool HALF_OUT>
__global__ void __launch_bounds__(256) gemm_mma_kernel(
    const float* __restrict__ X, const float* __restrict__ W,
    const float* __restrict__ bias, void* __restrict__ Yv, int nrows)
{
    extern __shared__ __half sh[];
    __half* As = sh;                    // [128][SPITCH]
    __half* Ws = sh + 128 * SPITCH;     // [128][SPITCH]

    const int tid  = threadIdx.x;
    const int lane = tid & 31;
    const int wid  = tid >> 5;
    const int wr   = wid >> 1;          // warp row group (0..3): rows wr*32..+31
    const int wc   = wid & 1;           // warp col group (0..1): cols wc*64..+63
    const int row0 = blockIdx.x * 128;

    // ---- stage X (rows, fp32->fp16) and W into smem ----
    #pragma unroll
    for (int it = 0; it < 16; it++) {
        int f = tid + it * 256;         // 4096 float4 total
        int r = f >> 5;                 // 0..127
        int q = f & 31;                 // float4 index in row
        int gr = row0 + r;
        float4 v = make_float4(0.f, 0.f, 0.f, 0.f);
        if (gr < nrows)
            v = *reinterpret_cast<const float4*>(X + (size_t)gr * HID + q * 4);
        __half2 h01 = __floats2half2_rn(v.x, v.y);
        __half2 h23 = __floats2half2_rn(v.z, v.w);
        uint2 pk;
        pk.x = *reinterpret_cast<uint32_t*>(&h01);
        pk.y = *reinterpret_cast<uint32_t*>(&h23);
        *reinterpret_cast<uint2*>(As + r * SPITCH + q * 4) = pk;
    }
    #pragma unroll
    for (int it = 0; it < 16; it++) {
        int f = tid + it * 256;
        int c = f >> 5;
        int q = f & 31;
        float4 v = *reinterpret_cast<const float4*>(W + c * HID + q * 4);
        __half2 h01 = __floats2half2_rn(v.x, v.y);
        __half2 h23 = __floats2half2_rn(v.z, v.w);
        uint2 pk;
        pk.x = *reinterpret_cast<uint32_t*>(&h01);
        pk.y = *reinterpret_cast<uint32_t*>(&h23);
        *reinterpret_cast<uint2*>(Ws + c * SPITCH + q * 4) = pk;
    }
    __syncthreads();

    // ---- fragment address precompute ----
    const int lr = lane & 7;
    const int lb = (lane >> 3) & 1;     // second 8-group selector
    const int lk = (lane >> 4) & 1;     // third/fourth matrix selector
    const uint32_t As_u = smem_u32(As);
    const uint32_t Ws_u = smem_u32(Ws);

    // A: matrices (rows0-7,k0-7)(rows8-15,k0-7)(rows0-7,k8-15)(rows8-15,k8-15)
    uint32_t a_addr[2];
    #pragma unroll
    for (int mt = 0; mt < 2; mt++)
        a_addr[mt] = As_u + (((wr * 32 + mt * 16 + lr + lb * 8) * SPITCH) + lk * 8) * 2;
    // B: matrices (n0-7,k0-7)(n0-7,k8-15)(n8-15,k0-7)(n8-15,k8-15)
    uint32_t b_addr[4];
    #pragma unroll
    for (int p = 0; p < 4; p++)
        b_addr[p] = Ws_u + (((wc * 64 + p * 16 + lk * 8 + lr) * SPITCH) + lb * 8) * 2;

    float acc[2][8][4];
    #pragma unroll
    for (int mt = 0; mt < 2; mt++)
        #pragma unroll
        for (int nt = 0; nt < 8; nt++)
            #pragma unroll
            for (int i = 0; i < 4; i++) acc[mt][nt][i] = 0.f;

    // ---- main loop: 8 k-steps of 16 ----
    #pragma unroll
    for (int ks = 0; ks < 8; ks++) {
        uint32_t a[2][4];
        #pragma unroll
        for (int mt = 0; mt < 2; mt++)
            ldsm4(a[mt][0], a[mt][1], a[mt][2], a[mt][3], a_addr[mt] + ks * 32);
        uint32_t b[4][4];
        #pragma unroll
        for (int p = 0; p < 4; p++)
            ldsm4(b[p][0], b[p][1], b[p][2], b[p][3], b_addr[p] + ks * 32);
        #pragma unroll
        for (int mt = 0; mt < 2; mt++)
            #pragma unroll
            for (int p = 0; p < 4; p++) {
                mma16816(acc[mt][2 * p],     a[mt][0], a[mt][1], a[mt][2], a[mt][3],
                         b[p][0], b[p][1]);
                mma16816(acc[mt][2 * p + 1], a[mt][0], a[mt][1], a[mt][2], a[mt][3],
                         b[p][2], b[p][3]);
            }
    }

    // ---- epilogue ----
    const int g = lane >> 2;
    const int q = lane & 3;
    #pragma unroll
    for (int mt = 0; mt < 2; mt++) {
        #pragma unroll
        for (int half_r = 0; half_r < 2; half_r++) {
            int R = row0 + wr * 32 + mt * 16 + g + half_r * 8;
            if (R < nrows) {
                #pragma unroll
                for (int nt = 0; nt < 8; nt++) {
                    int col = wc * 64 + nt * 8 + 2 * q;
                    float v0 = acc[mt][nt][2 * half_r];
                    float v1 = acc[mt][nt][2 * half_r + 1];
                    if (bias) { v0 += bias[col]; v1 += bias[col + 1]; }
                    if (HALF_OUT) {
                        __half2 h = __floats2half2_rn(v0, v1);
                        *reinterpret_cast<__half2*>(
                            reinterpret_cast<__half*>(Yv) + (size_t)R * HID + col) = h;
                    } else {
                        *reinterpret_cast<float2*>(
                            reinterpret_cast<float*>(Yv) + (size_t)R * HID + col) =
                            make_float2(v0, v1);
                    }
                }
            }
        }
    }
}

// ---------------- CSR build ----------------
__global__ void hist_kernel(const int* __restrict__ dst, int n, int* __restrict__ cnt)
{
    int i = blockIdx.x * blockDim.x + threadIdx.x;
    if (i < n) atomicAdd(cnt + __ldg(dst + i), 1);
}

__global__ void __launch_bounds__(1024) scan1_kernel(const int* __restrict__ in,
                                                     int* __restrict__ out,
                                                     int* __restrict__ bsum, int n)
{
    __shared__ int sh[1024];
    int base = blockIdx.x * 4096 + threadIdx.x * 4;
    int4 v = make_int4(0, 0, 0, 0);
    if (base < n) v = *reinterpret_cast<const int4*>(in + base);   // n divisible by 4
    int s = v.x + v.y + v.z + v.w;
    sh[threadIdx.x] = s;
    __syncthreads();
    for (int d = 1; d < 1024; d <<= 1) {
        int t = (threadIdx.x >= d) ? sh[threadIdx.x - d] : 0;
        __syncthreads();
        sh[threadIdx.x] += t;
        __syncthreads();
    }
    if (threadIdx.x == 1023) bsum[blockIdx.x] = sh[1023];
    int e = sh[threadIdx.x] - s;                                   // exclusive
    if (base < n) {
        int4 o;
        o.x = e; o.y = e + v.x; o.z = o.y + v.y; o.w = o.z + v.z;
        *reinterpret_cast<int4*>(out + base) = o;
    }
}

__global__ void __launch_bounds__(1024) scan2_kernel(int* __restrict__ bsum, int nb)
{
    __shared__ int sh[1024];
    int v = (threadIdx.x < nb) ? bsum[threadIdx.x] : 0;
    sh[threadIdx.x] = v;
    __syncthreads();
    for (int d = 1; d < 1024; d <<= 1) {
        int t = (threadIdx.x >= d) ? sh[threadIdx.x - d] : 0;
        __syncthreads();
        sh[threadIdx.x] += t;
        __syncthreads();
    }
    if (threadIdx.x < nb) bsum[threadIdx.x] = sh[threadIdx.x] - v; // exclusive
}

__global__ void __launch_bounds__(1024) scan3_kernel(int* __restrict__ out,
                                                     int* __restrict__ cur,
                                                     const int* __restrict__ bsum, int n)
{
    int base = blockIdx.x * 4096 + threadIdx.x * 4;
    if (base < n) {
        int a = bsum[blockIdx.x];
        int4 v = *reinterpret_cast<int4*>(out + base);
        v.x += a; v.y += a; v.z += a; v.w += a;
        *reinterpret_cast<int4*>(out + base) = v;
        *reinterpret_cast<int4*>(cur + base) = v;
    }
}

__global__ void fill_kernel(const int* __restrict__ src, const int* __restrict__ dst,
                            int n, int* __restrict__ cur, int yofs)
{
    int i = blockIdx.x * blockDim.x + threadIdx.x;
    if (i < n) {
        int d = __ldg(dst + i);
        int p = atomicAdd(cur + d, 1);
        g_eidx[p] = yofs + __ldg(src + i);
    }
}

// ---------------- gather: warp per job; fp16 rows; 2 edges per iteration ----------------
__global__ void __launch_bounds__(256) gather_kernel(const __half* __restrict__ y,
                                                     float* __restrict__ out, int njob)
{
    int g = blockIdx.x * blockDim.x + threadIdx.x;
    int j = g >> 5;
    if (j >= njob) return;
    int lane = g & 31;
    int sub  = lane >> 4;       // which edge of the pair
    int hl   = lane & 15;       // column block: cols hl*8 .. +7

    float acc[8];
    #pragma unroll
    for (int i = 0; i < 8; i++) acc[i] = 0.f;

    #pragma unroll
    for (int r = 0; r < 5; r++) {
        int idx   = r * NJOB + j;
        int c     = __ldg(g_icnt + idx);
        int start = __ldg(g_off  + idx);
        float s8[8];
        #pragma unroll
        for (int i = 0; i < 8; i++) s8[i] = 0.f;

        for (int b = 0; b < c; b += 32) {
            int nn = c - b; if (nn > 32) nn = 32;
            int ei = 0;
            if (lane < nn) ei = __ldg(g_eidx + start + b + lane);
            for (int k = 0; k < nn; k += 2) {
                int kk = k + sub;
                int row = __shfl_sync(0xffffffffu, ei, kk);
                if (kk < nn) {
                    uint4 v = __ldg(reinterpret_cast<const uint4*>(
                        y + (size_t)row * HID + hl * 8));
                    const __half2* h2 = reinterpret_cast<const __half2*>(&v);
                    #pragma unroll
                    for (int t = 0; t < 4; t++) {
                        float2 f = __half22float2(h2[t]);
                        s8[2 * t]     += f.x;
                        s8[2 * t + 1] += f.y;
                    }
                }
            }
        }
        float inv = 1.0f / fmaxf((float)c, 1.0f);
        #pragma unroll
        for (int i = 0; i < 8; i++) acc[i] = fmaf(s8[i], inv, acc[i]);
    }

    #pragma unroll
    for (int i = 0; i < 8; i++) acc[i] += __shfl_xor_sync(0xffffffffu, acc[i], 16);

    if (lane < 16) {
        float4* op = reinterpret_cast<float4*>(out + (size_t)j * HID + hl * 8);
        float4 o0 = op[0];
        float4 o1 = op[1];
        o0.x = fmaxf(o0.x + acc[0], 0.f); o0.y = fmaxf(o0.y + acc[1], 0.f);
        o0.z = fmaxf(o0.z + acc[2], 0.f); o0.w = fmaxf(o0.w + acc[3], 0.f);
        o1.x = fmaxf(o1.x + acc[4], 0.f); o1.y = fmaxf(o1.y + acc[5], 0.f);
        o1.z = fmaxf(o1.z + acc[6], 0.f); o1.w = fmaxf(o1.w + acc[7], 0.f);
        op[0] = o0;
        op[1] = o1;
    }
}

// ---------------- host ----------------
extern "C" void kernel_launch(void* const* d_in, const int* in_sizes, int n_in,
                              void* d_out, int out_size)
{
    const float* x_job = (const float*)d_in[0];
    const float* xtab[5];
    xtab[0] = (const float*)d_in[1];  // station
    xtab[1] = (const float*)d_in[1];  // station
    xtab[2] = (const float*)d_in[2];  // machine
    xtab[3] = (const float*)d_in[2];  // machine
    xtab[4] = (const float*)d_in[3];  // robot
    int nsrc[5];
    nsrc[0] = in_sizes[1] / HID; nsrc[1] = nsrc[0];
    nsrc[2] = in_sizes[2] / HID; nsrc[3] = nsrc[2];
    nsrc[4] = in_sizes[3] / HID;
    int yofs[5];
    yofs[0] = 0;
    for (int r = 1; r < 5; r++) yofs[r] = yofs[r - 1] + nsrc[r - 1];

    const int *src[5], *dst[5];
    const float *Wl[5], *bl[5], *Wr[5];
    int nedge[5];
    // Detect input ordering: dict order (src,dst,Wl,bl,Wr per relation) has a
    // 16384-element tensor at index 6; signature order has 800000 there.
    bool dict = (in_sizes[6] == HID * HID);
    for (int r = 0; r < 5; r++) {
        if (dict) {
            src[r] = (const int*)d_in[4 + 5 * r];
            dst[r] = (const int*)d_in[5 + 5 * r];
            Wl[r]  = (const float*)d_in[6 + 5 * r];
            bl[r]  = (const float*)d_in[7 + 5 * r];
            Wr[r]  = (const float*)d_in[8 + 5 * r];
            nedge[r] = in_sizes[4 + 5 * r];
        } else {
            src[r] = (const int*)d_in[4 + 2 * r];
            dst[r] = (const int*)d_in[5 + 2 * r];
            Wl[r]  = (const float*)d_in[14 + 3 * r];
            bl[r]  = (const float*)d_in[15 + 3 * r];
            Wr[r]  = (const float*)d_in[16 + 3 * r];
            nedge[r] = in_sizes[4 + 2 * r];
        }
    }

    __half* yp;
    float *WrSp, *blSp;
    int *icntp, *offp, *curp, *bsump;
    cudaGetSymbolAddress((void**)&yp,    g_y);
    cudaGetSymbolAddress((void**)&WrSp,  g_WrS);
    cudaGetSymbolAddress((void**)&blSp,  g_blS);
    cudaGetSymbolAddress((void**)&icntp, g_icnt);
    cudaGetSymbolAddress((void**)&offp,  g_off);
    cudaGetSymbolAddress((void**)&curp,  g_cur);
    cudaGetSymbolAddress((void**)&bsump, g_bsum);

    const int SMEMB = 2 * 128 * SPITCH * (int)sizeof(__half);  // 69632 B
    cudaFuncSetAttribute(gemm_mma_kernel<false>,
                         cudaFuncAttributeMaxDynamicSharedMemorySize, SMEMB);
    cudaFuncSetAttribute(gemm_mma_kernel<true>,
                         cudaFuncAttributeMaxDynamicSharedMemorySize, SMEMB);

    int njob = out_size / HID;
    int n5 = 5 * njob;                      // count-array length (divisible by 4)
    int nb = (n5 + 4095) / 4096;            // scan blocks (<= 256)

    // Fold all 5 Wr + biases into one matrix/vector.
    sum_wr_kernel<<<64, 256>>>(Wr[0], Wr[1], Wr[2], Wr[3], Wr[4],
                               bl[0], bl[1], bl[2], bl[3], bl[4]);

    // Zero per-(rel,job) counters.
    zero4_kernel<<<(n5 / 4 + 255) / 256, 256>>>(reinterpret_cast<int4*>(icntp), n5 / 4);

    // Base term: out = x_job @ WrS^T + blS (also initializes poisoned d_out).
    gemm_mma_kernel<false><<<(njob + 127) / 128, 256, SMEMB>>>(
        x_job, WrSp, blSp, d_out, njob);

    // Transform all source tables: y_r = x_src_r @ Wl_r^T (fp16 output).
    for (int r = 0; r < 5; r++)
        gemm_mma_kernel<true><<<(nsrc[r] + 127) / 128, 256, SMEMB>>>(
            xtab[r], Wl[r], nullptr, yp + (size_t)yofs[r] * HID, nsrc[r]);

    // Histogram destinations per relation.
    for (int r = 0; r < 5; r++)
        hist_kernel<<<(nedge[r] + 255) / 256, 256>>>(dst[r], nedge[r], icntp + r * NJOB);

    // Global exclusive scan over all 5*njob counts (region bases fall out).
    scan1_kernel<<<nb, 1024>>>(icntp, offp, bsump, n5);
    scan2_kernel<<<1, 1024>>>(bsump, nb);
    scan3_kernel<<<nb, 1024>>>(offp, curp, bsump, n5);

    // Fill CSR payload (y-row index, relation offset folded in).
    for (int r = 0; r < 5; r++)
        fill_kernel<<<(nedge[r] + 255) / 256, 256>>>(src[r], dst[r], nedge[r],
                                                     curp + r * NJOB, yofs[r]);

    // Gather + mean + base + relu, one pass.
    gather_kernel<<<(njob * 32 + 255) / 256, 256>>>(yp, (float*)d_out, njob);
}